// round 14
// baseline (speedup 1.0000x reference)
#include <cuda_runtime.h>
#include <cuda_bf16.h>

// Sinkhorn EMD, N=M=1024, D=3, eps=0.01, iters read from input (3000).
// Persistent kernel, 128 CTAs x 256 threads; warp w of CTA b owns row b*8+w.
//
// Semantics are IDENTICAL to R13 (passed, rel_err 1.06e-7): fence-free
// barrier with exch-commit dependency folded into the arrival, volatile
// global reads for f/g (true L1 bypass). The only change vs R13 is
// SCHEDULING: the volatile-load wrappers no longer carry a "memory"
// clobber (which made each load a compiler barrier => MLP=1, ~2600 cyc of
// serialized L2 latency per half-pass). Loads are now front-batched into
// registers (8 x ld.volatile.global.v4 in flight), then C is subtracted
// in place from SMEM.
//
//  WRITER:  lane0: old = atomicExch(&dout[row], bits)   // commits at L2
//                  sh_dep[w] = old & zmask               // STS stalls on old
//           __syncthreads()                              // drains STS
//           tid0:  atomicAdd(&d_cnt, 1 + OR(sh_dep))     // happens-after exch
//  READER:  ld.volatile.global.v4 (L1 bypass, no fence needed)
//  Barrier: flat monotone d_cnt, monotone d_gen release, equality spins,
//           per-launch base snapshot => graph-replay safe without resets.
//
// Math in the exp2 domain scaled by S = log2(e)/eps (S*eps*ln2 == 1,
// S*eps*ln(1024) == 10):  S*f_row = -10 - m - log2(sum_j exp2(args_j - m)).

#define Nn      1024
#define NCTA    128
#define NTH     256
#define S_CONST 144.26950408889634074f   // log2(e)/eps, eps = 0.01
#define INV_S   0.0069314718055994531f   // eps*ln2 = 1/S

#define SMEM_BYTES (8 * 1024 * 2 * 4)    // sSC + sSCT = 64 KB

__device__ __align__(16) float d_Sf[Nn];      // S * f
__device__ __align__(16) float d_Sg[Nn];      // S * g
__device__ __align__(16) float d_rowsum[Nn];
__device__ unsigned d_cnt  = 0;               // monotone arrival counter
__device__ unsigned d_gen  = 0;               // monotone release word
__device__ unsigned d_zero = 0;               // never written: opaque 0 for dep chains

__device__ __forceinline__ float ex2f(float x) {
    float r;
    asm("ex2.approx.ftz.f32 %0, %1;" : "=f"(r) : "f"(x));
    return r;
}
// Volatile loads WITHOUT a memory clobber: cannot be eliminated or reordered
// among themselves, but CAN be scheduled back-to-back (MLP restored).
__device__ __forceinline__ float4 ldvol_f4(const float4* p) {
    float4 v;
    asm volatile("ld.volatile.global.v4.f32 {%0,%1,%2,%3}, [%4];"
                 : "=f"(v.x), "=f"(v.y), "=f"(v.z), "=f"(v.w) : "l"(p));
    return v;
}
__device__ __forceinline__ float ldvol_f(const float* p) {
    float v;
    asm volatile("ld.volatile.global.f32 %0, [%1];" : "=f"(v) : "l"(p));
    return v;
}

// Fence-free grid barrier (R13-verbatim, proven). m = absolute barrier index.
__device__ __forceinline__ void grid_bar(unsigned m, volatile unsigned* sh_dep) {
    __syncthreads();                                // drains dep STS
    if (threadIdx.x == 0) {
        const unsigned extra = sh_dep[0] | sh_dep[1] | sh_dep[2] | sh_dep[3]
                             | sh_dep[4] | sh_dep[5] | sh_dep[6] | sh_dep[7];
        const unsigned want = m + 1u;
        unsigned prev = atomicAdd(&d_cnt, 1u + extra);   // extra == 0, data-dep
        if (prev == m * (unsigned)NCTA + (unsigned)(NCTA - 1))
            *(volatile unsigned*)&d_gen = want;          // release (last arrival)
        while (*(volatile unsigned*)&d_gen != want) { }
    }
    __syncthreads();
}

// One Sinkhorn half-update, warp-independent. Loads are front-batched.
//   dout[row] = -10 - m - log2( sum_j exp2( din[j] - sC[w][j] - m ) )
template <bool HASG>
__device__ __forceinline__ void half_pass(const float* __restrict__ sC,
                                          const float* __restrict__ din, // global
                                          float* __restrict__ dout,      // global
                                          volatile unsigned* sh_dep, unsigned zmask,
                                          int w, int lane, int row) {
    const float4* c4 = (const float4*)(sC + (w << 10));
    const float4* g4 = (const float4*)din;
    float4 a[8];
    // Phase 1: batch all 8 volatile staging loads (8 in flight).
#pragma unroll
    for (int k = 0; k < 8; k++)
        a[k] = HASG ? ldvol_f4(g4 + ((k << 5) + lane))
                    : make_float4(0.f, 0.f, 0.f, 0.f);
    // Phase 2: subtract SMEM-resident C in place; track max.
    float m = -3.4e38f;
#pragma unroll
    for (int k = 0; k < 8; k++) {
        const float4 c = c4[(k << 5) + lane];           // LDS.128, conflict-free
        a[k].x -= c.x; a[k].y -= c.y; a[k].z -= c.z; a[k].w -= c.w;
        m = fmaxf(m, fmaxf(fmaxf(a[k].x, a[k].y), fmaxf(a[k].z, a[k].w)));
    }
#pragma unroll
    for (int off = 16; off; off >>= 1)
        m = fmaxf(m, __shfl_xor_sync(0xffffffffu, m, off));
    float sum = 0.f;
#pragma unroll
    for (int k = 0; k < 8; k++) {
        sum += ex2f(a[k].x - m);
        sum += ex2f(a[k].y - m);
        sum += ex2f(a[k].z - m);
        sum += ex2f(a[k].w - m);
    }
#pragma unroll
    for (int off = 16; off; off >>= 1)
        sum += __shfl_xor_sync(0xffffffffu, sum, off);
    if (lane == 0) {
        const float val = -10.0f - m - __log2f(sum);
        unsigned old = atomicExch((unsigned*)&dout[row], __float_as_uint(val));
        sh_dep[w] = old & zmask;   // STS stalls on 'old' => exch committed at L2
    }
}

__global__ void __launch_bounds__(NTH, 1)
emd_kernel(const float* __restrict__ tgt,    // [1024,3]
           const float* __restrict__ outp,   // [1024,3]
           const int*   __restrict__ iters_ptr,
           float*       __restrict__ out) {
    extern __shared__ __align__(16) float smem[];
    float* sSC  = smem;                // [8][1024]  S*C rows
    float* sSCT = smem + 8 * 1024;     // [8][1024]  S*C^T rows
    __shared__ float red[NTH];
    __shared__ unsigned sh_base;
    __shared__ volatile unsigned sh_dep[8];

    const int tid  = threadIdx.x;
    const int w    = tid >> 5;
    const int lane = tid & 31;
    const int bid  = (int)blockIdx.x;
    const int row  = (bid << 3) + w;

    // Per-launch base snapshot of the monotone release word (proven pattern).
    if (tid == 0) sh_base = *(volatile unsigned*)&d_gen;
    if (tid < 8)  sh_dep[tid] = 0u;
    const unsigned zmask = *(volatile unsigned*)&d_zero;   // opaque 0

    // ---- Phase A (CTA-local): build SMEM cost slices from point clouds ----
    {
        const float tx = tgt[row * 3 + 0], ty = tgt[row * 3 + 1], tz = tgt[row * 3 + 2];
        for (int j = lane; j < Nn; j += 32) {
            const float dx = tx - outp[j * 3 + 0];
            const float dy = ty - outp[j * 3 + 1];
            const float dz = tz - outp[j * 3 + 2];
            sSC[(w << 10) + j] = S_CONST * (dx * dx + dy * dy + dz * dz);
        }
        const float ox = outp[row * 3 + 0], oy = outp[row * 3 + 1], oz = outp[row * 3 + 2];
        for (int i = lane; i < Nn; i += 32) {
            const float dx = tgt[i * 3 + 0] - ox;
            const float dy = tgt[i * 3 + 1] - oy;
            const float dz = tgt[i * 3 + 2] - oz;
            sSCT[(w << 10) + i] = S_CONST * (dx * dx + dy * dy + dz * dz);
        }
    }
    __syncthreads();
    const unsigned base = sh_base;

    // ---- Phase B: Sinkhorn iterations ----
    const int iters = iters_ptr ? iters_ptr[0] : 3000;
    unsigned k = 0;
    {   // iteration 0: g == 0
        half_pass<false>(sSC, (const float*)0, d_Sf, sh_dep, zmask, w, lane, row);
        grid_bar(base + (k++), sh_dep);
        half_pass<true>(sSCT, d_Sf, d_Sg, sh_dep, zmask, w, lane, row);
        grid_bar(base + (k++), sh_dep);
    }
    for (int it = 1; it < iters; it++) {
        half_pass<true>(sSC,  d_Sg, d_Sf, sh_dep, zmask, w, lane, row);
        grid_bar(base + (k++), sh_dep);
        half_pass<true>(sSCT, d_Sf, d_Sg, sh_dep, zmask, w, lane, row);
        grid_bar(base + (k++), sh_dep);
    }

    // ---- Phase C: rowsum_i = sum_j exp2(Sf_i + Sg_j - SC_ij) * SC_ij ----
    {
        const float sfr = ldvol_f(&d_Sf[row]);
        const float4* c4 = (const float4*)(sSC + (w << 10));
        const float4* g4 = (const float4*)d_Sg;
        float4 a[8];
#pragma unroll
        for (int kk = 0; kk < 8; kk++)
            a[kk] = ldvol_f4(g4 + ((kk << 5) + lane));
        float acc = 0.f;
#pragma unroll
        for (int kk = 0; kk < 8; kk++) {
            const float4 c = c4[(kk << 5) + lane];
            acc += ex2f(sfr + a[kk].x - c.x) * c.x;
            acc += ex2f(sfr + a[kk].y - c.y) * c.y;
            acc += ex2f(sfr + a[kk].z - c.z) * c.z;
            acc += ex2f(sfr + a[kk].w - c.w) * c.w;
        }
#pragma unroll
        for (int off = 16; off; off >>= 1)
            acc += __shfl_xor_sync(0xffffffffu, acc, off);
        if (lane == 0) {
            unsigned old = atomicExch((unsigned*)&d_rowsum[row], __float_as_uint(acc));
            sh_dep[w] = old & zmask;
        }
    }
    grid_bar(base + (k++), sh_dep);

    // ---- Deterministic final reduction by CTA 0; scale by 1/S ----
    if (bid == 0) {
        float v = 0.f;
        for (int i = tid; i < Nn; i += NTH) v += ldvol_f(&d_rowsum[i]);
        red[tid] = v;
        __syncthreads();
        for (int s = NTH >> 1; s > 0; s >>= 1) {
            if (tid < s) red[tid] += red[tid + s];
            __syncthreads();
        }
        if (tid == 0) out[0] = red[0] * INV_S;
    }
    // d_cnt and d_gen are monotone with per-launch base snapshot and equality
    // spins => graph replays need no reset handshake.
}

extern "C" void kernel_launch(void* const* d_in, const int* in_sizes, int n_in,
                              void* d_out, int out_size) {
    const float* tgt  = (const float*)d_in[0];
    const float* outp = (const float*)d_in[1];
    const int*   itp  = (n_in >= 3) ? (const int*)d_in[2] : nullptr;
    (void)in_sizes; (void)out_size;
    cudaFuncSetAttribute(emd_kernel, cudaFuncAttributeMaxDynamicSharedMemorySize,
                         SMEM_BYTES);
    emd_kernel<<<NCTA, NTH, SMEM_BYTES>>>(tgt, outp, itp, (float*)d_out);
}

// round 15
// speedup vs baseline: 1.1518x; 1.1518x over previous
#include <cuda_runtime.h>
#include <cuda_bf16.h>

// Sinkhorn EMD, N=M=1024, D=3, eps=0.01, iters read from input (3000).
// Persistent kernel, 128 CTAs x 256 threads; warp w of CTA b owns row b*8+w.
//
// Structure is R12-verbatim (passed, 11.70ms, rel_err 1.06e-7) EXCEPT the
// grid barrier now uses the official PTX acquire/release protocol instead of
// __threadfence (fence.sc.gpu ~1400 cyc):
//
//   publish:  plain STG of the 8 row values
//   arrive:   __syncthreads; tid0: atom.acq_rel.gpu.global.add.u32 d_cnt
//             (release cumulative over the BAR => all this CTA's stores are
//              visible before the arrival is; acquire folds prior releases)
//   release:  last arrival: st.release.gpu.global.u32 d_gen = m+1
//   wait:     tid0 spins with ld.acquire.gpu.global.u32 on d_gen; the acquire
//             synchronizes-with the release, so the post-barrier PLAIN staging
//             loads (L1/MSHR-dedup friendly, no L2 hotspot) are guaranteed
//             fresh by the PTX memory model; __syncthreads propagates to the
//             other warps.  "memory" clobbers stop compiler hoisting.
//
// d_cnt/d_gen are monotone with per-launch base snapshot and equality spins
// => graph-replay safe with no reset handshake (proven pattern).
//
// Math in the exp2 domain scaled by S = log2(e)/eps (S*eps*ln2 == 1,
// S*eps*ln(1024) == 10):  S*f_row = -10 - m - log2(sum_j exp2(args_j - m)).

#define Nn      1024
#define NCTA    128
#define NTH     256
#define S_CONST 144.26950408889634074f   // log2(e)/eps, eps = 0.01
#define INV_S   0.0069314718055994531f   // eps*ln2 = 1/S

#define SMEM_BYTES (8 * 1024 * 2 * 4)    // sSC + sSCT = 64 KB

__device__ __align__(16) float d_Sf[Nn];      // S * f
__device__ __align__(16) float d_Sg[Nn];      // S * g
__device__ __align__(16) float d_rowsum[Nn];
__device__ unsigned d_cnt = 0;                 // monotone arrival counter
__device__ unsigned d_gen = 0;                 // monotone release word

__device__ __forceinline__ float ex2f(float x) {
    float r;
    asm("ex2.approx.ftz.f32 %0, %1;" : "=f"(r) : "f"(x));
    return r;
}

__device__ __forceinline__ unsigned atom_add_acqrel(unsigned* p, unsigned v) {
    unsigned old;
    asm volatile("atom.acq_rel.gpu.global.add.u32 %0, [%1], %2;"
                 : "=r"(old) : "l"(p), "r"(v) : "memory");
    return old;
}
__device__ __forceinline__ void st_release(unsigned* p, unsigned v) {
    asm volatile("st.release.gpu.global.u32 [%0], %1;" :: "l"(p), "r"(v) : "memory");
}
__device__ __forceinline__ unsigned ld_acquire(const unsigned* p) {
    unsigned v;
    asm volatile("ld.acquire.gpu.global.u32 %0, [%1];" : "=r"(v) : "l"(p) : "memory");
    return v;
}
__device__ __forceinline__ unsigned ld_relaxed(const unsigned* p) {
    unsigned v;
    asm volatile("ld.relaxed.gpu.global.u32 %0, [%1];" : "=r"(v) : "l"(p) : "memory");
    return v;
}

// Acquire/release grid barrier. m = absolute barrier index (monotone across
// graph replays). Wrap-safe (equality comparisons only).
__device__ __forceinline__ void grid_bar(unsigned m) {
    __syncthreads();                                    // CTA's publishes ordered
    if (threadIdx.x == 0) {
        const unsigned want = m + 1u;
        unsigned prev = atom_add_acqrel(&d_cnt, 1u);    // release-arrive
        if (prev == m * (unsigned)NCTA + (unsigned)(NCTA - 1))
            st_release(&d_gen, want);                   // release to all
        while (ld_acquire(&d_gen) != want) { }          // acquire-wait
    }
    __syncthreads();
}

// One Sinkhorn half-update, warp-independent (R12-verbatim compute).
//   dout[row] = -10 - m - log2( sum_j exp2( din[j] - sC[w][j] - m ) )
template <bool HASG>
__device__ __forceinline__ void half_pass(const float* __restrict__ sC,
                                          const float* __restrict__ din, // global
                                          float* __restrict__ dout,      // global
                                          int w, int lane, int row) {
    const float4* c4 = (const float4*)(sC + (w << 10));
    const float4* g4 = (const float4*)din;
    float args[32];
    float m = -3.4e38f;
#pragma unroll
    for (int k = 0; k < 8; k++) {
        const int idx = (k << 5) + lane;
        const float4 c = c4[idx];                       // LDS.128, conflict-free
        const float4 g = HASG ? g4[idx]                 // plain LDG.128 (fresh via acquire)
                              : make_float4(0.f, 0.f, 0.f, 0.f);
        const float a0 = g.x - c.x;
        const float a1 = g.y - c.y;
        const float a2 = g.z - c.z;
        const float a3 = g.w - c.w;
        args[4 * k + 0] = a0; args[4 * k + 1] = a1;
        args[4 * k + 2] = a2; args[4 * k + 3] = a3;
        m = fmaxf(m, fmaxf(fmaxf(a0, a1), fmaxf(a2, a3)));
    }
#pragma unroll
    for (int off = 16; off; off >>= 1)
        m = fmaxf(m, __shfl_xor_sync(0xffffffffu, m, off));
    float sum = 0.f;
#pragma unroll
    for (int k = 0; k < 32; k++) sum += ex2f(args[k] - m);
#pragma unroll
    for (int off = 16; off; off >>= 1)
        sum += __shfl_xor_sync(0xffffffffu, sum, off);
    if (lane == 0)
        dout[row] = -10.0f - m - __log2f(sum);   // plain store, released at arrival
}

__global__ void __launch_bounds__(NTH, 1)
emd_kernel(const float* __restrict__ tgt,    // [1024,3]
           const float* __restrict__ outp,   // [1024,3]
           const int*   __restrict__ iters_ptr,
           float*       __restrict__ out) {
    extern __shared__ __align__(16) float smem[];
    float* sSC  = smem;                // [8][1024]  S*C rows
    float* sSCT = smem + 8 * 1024;     // [8][1024]  S*C^T rows
    __shared__ float red[NTH];
    __shared__ unsigned sh_base;

    const int tid  = threadIdx.x;
    const int w    = tid >> 5;
    const int lane = tid & 31;
    const int bid  = (int)blockIdx.x;
    const int row  = (bid << 3) + w;

    // Per-launch base snapshot of the monotone release word (proven pattern;
    // safe: d_gen cannot advance before ALL CTAs arrive at barrier 0, which
    // is after every CTA's snapshot).
    if (tid == 0) sh_base = ld_relaxed(&d_gen);

    // ---- Phase A (CTA-local): build SMEM cost slices from point clouds ----
    {
        const float tx = tgt[row * 3 + 0], ty = tgt[row * 3 + 1], tz = tgt[row * 3 + 2];
        for (int j = lane; j < Nn; j += 32) {
            const float dx = tx - outp[j * 3 + 0];
            const float dy = ty - outp[j * 3 + 1];
            const float dz = tz - outp[j * 3 + 2];
            sSC[(w << 10) + j] = S_CONST * (dx * dx + dy * dy + dz * dz);
        }
        const float ox = outp[row * 3 + 0], oy = outp[row * 3 + 1], oz = outp[row * 3 + 2];
        for (int i = lane; i < Nn; i += 32) {
            const float dx = tgt[i * 3 + 0] - ox;
            const float dy = tgt[i * 3 + 1] - oy;
            const float dz = tgt[i * 3 + 2] - oz;
            sSCT[(w << 10) + i] = S_CONST * (dx * dx + dy * dy + dz * dz);
        }
    }
    __syncthreads();
    const unsigned base = sh_base;

    // ---- Phase B: Sinkhorn iterations ----
    const int iters = iters_ptr ? iters_ptr[0] : 3000;
    unsigned k = 0;
    {   // iteration 0: g == 0
        half_pass<false>(sSC, (const float*)0, d_Sf, w, lane, row);
        grid_bar(base + (k++));
        half_pass<true>(sSCT, d_Sf, d_Sg, w, lane, row);
        grid_bar(base + (k++));
    }
    for (int it = 1; it < iters; it++) {
        half_pass<true>(sSC,  d_Sg, d_Sf, w, lane, row);
        grid_bar(base + (k++));
        half_pass<true>(sSCT, d_Sf, d_Sg, w, lane, row);
        grid_bar(base + (k++));
    }

    // ---- Phase C: rowsum_i = sum_j exp2(Sf_i + Sg_j - SC_ij) * SC_ij ----
    {
        const float sfr = d_Sf[row];
        const float4* c4 = (const float4*)(sSC + (w << 10));
        const float4* g4 = (const float4*)d_Sg;
        float acc = 0.f;
#pragma unroll
        for (int kk = 0; kk < 8; kk++) {
            const int idx = (kk << 5) + lane;
            const float4 c = c4[idx];
            const float4 g = g4[idx];
            acc += ex2f(sfr + g.x - c.x) * c.x;
            acc += ex2f(sfr + g.y - c.y) * c.y;
            acc += ex2f(sfr + g.z - c.z) * c.z;
            acc += ex2f(sfr + g.w - c.w) * c.w;
        }
#pragma unroll
        for (int off = 16; off; off >>= 1)
            acc += __shfl_xor_sync(0xffffffffu, acc, off);
        if (lane == 0) d_rowsum[row] = acc;
    }
    grid_bar(base + (k++));

    // ---- Deterministic final reduction by CTA 0; scale by 1/S ----
    if (bid == 0) {
        float v = 0.f;
        for (int i = tid; i < Nn; i += NTH) v += d_rowsum[i];
        red[tid] = v;
        __syncthreads();
        for (int s = NTH >> 1; s > 0; s >>= 1) {
            if (tid < s) red[tid] += red[tid + s];
            __syncthreads();
        }
        if (tid == 0) out[0] = red[0] * INV_S;
    }
    // d_cnt and d_gen are monotone with per-launch base snapshot and equality
    // spins => graph replays need no reset handshake.
}

extern "C" void kernel_launch(void* const* d_in, const int* in_sizes, int n_in,
                              void* d_out, int out_size) {
    const float* tgt  = (const float*)d_in[0];
    const float* outp = (const float*)d_in[1];
    const int*   itp  = (n_in >= 3) ? (const int*)d_in[2] : nullptr;
    (void)in_sizes; (void)out_size;
    cudaFuncSetAttribute(emd_kernel, cudaFuncAttributeMaxDynamicSharedMemorySize,
                         SMEM_BYTES);
    emd_kernel<<<NCTA, NTH, SMEM_BYTES>>>(tgt, outp, itp, (float*)d_out);
}